// round 11
// baseline (speedup 1.0000x reference)
#include <cuda_runtime.h>
#include <math.h>

#define NB   36
#define NB2  72
#define SS   7
#define NOUT (2*NB + 2)  // 74

// One block per batch b, 224 threads = 7 warps; warp w handles s=w.
// Lane l owns k=l; lanes 0-3 also own k2=32+l.
// T[idx] staged as a straight float4 copy (unpadded): stride-36 rows are
// conflict-free for LDS.128 (banks 4l..4l+3 per 8-lane phase cover all 32).
__global__ __launch_bounds__(224, 4)
void deepwarping_kernel(const float* __restrict__ ll1,   // [B,S,NB]
                        const float* __restrict__ ll2,   // [B,S,NB]
                        const float* __restrict__ inp,   // [B,S,NB]
                        const float* __restrict__ yaw,   // [B]
                        const float* __restrict__ T,     // [61,NB,NB]
                        const float* __restrict__ M,     // [NB,NB] (circulant)
                        const float* __restrict__ pop,   // [2,NB]
                        float* __restrict__ out)         // [B,S,NOUT]
{
    const int b    = blockIdx.x;
    const int tid  = threadIdx.x;
    const int s    = tid >> 5;              // warp id = s (0..6)
    const int lane = tid & 31;

    __shared__ float sT  [NB * NB];         // yaw-selected transform, unpadded
    __shared__ float se1 [SS][NB];          // exp(ll1), per-warp row
    __shared__ float se2d[SS][NB2];         // exp(ll2) doubled, per-warp row
    __shared__ float si  [SS][NB];          // inp, per-warp row

    const int base = (b * SS + s) * NB;     // 16B-aligned

    // ---- independent front-batched loads ----
    const float yv = __ldg(yaw + b);

    const int  k    = lane;
    const int  k2   = 32 + (lane & 3);
    const bool has2 = lane < 4;

    const float eMk   = __expf(__ldg(M + k));     // circulant: M[0][k]
    const float eMk2  = __expf(__ldg(M + k2));
    const float popc  = __ldg(pop + k);
    const float pops  = __ldg(pop + NB + k);
    const float popc2 = __ldg(pop + k2);
    const float pops2 = __ldg(pop + NB + k2);

    // per-warp input staging: lanes 0-8 ll1, 9-17 ll2(doubled), 18-26 inp
    if (lane < 9) {
        float4 a = ((const float4*)(ll1 + base))[lane];
        ((float4*)se1[s])[lane] =
            make_float4(__expf(a.x), __expf(a.y), __expf(a.z), __expf(a.w));
    } else if (lane < 18) {
        const int q = lane - 9;
        float4 c = ((const float4*)(ll2 + base))[q];
        float4 e = make_float4(__expf(c.x), __expf(c.y), __expf(c.z), __expf(c.w));
        ((float4*)(se2d[s]))[q]      = e;
        ((float4*)(se2d[s] + NB))[q] = e;
    } else if (lane < 27) {
        const int q = lane - 18;
        ((float4*)si[s])[q] = ((const float4*)(inp + base))[q];
    }

    // block-wide cooperative T staging: straight float4 copy, 324 over 224 thr
    const int idx = 30 + (int)rintf(yv * (180.0f / 3.14159265358979323846f));
    {
        const float4* T4 = (const float4*)(T + idx * NB * NB);
        float4*       S4 = (float4*)sT;
        #pragma unroll
        for (int t = tid; t < (NB * NB) / 4; t += 224) {
            S4[t] = T4[t];
        }
    }

    __syncwarp();   // per-warp input rows ready

    // ---- s_k (and s_k2) : circular cross-correlation, wrap-free ----
    float sa0 = 0.f, sa1 = 0.f, sb0 = 0.f, sb1 = 0.f;
    #pragma unroll
    for (int i = 0; i < NB; i += 2) {
        const float e1a = se1[s][i];
        const float e1b = se1[s][i + 1];
        sa0 += e1a * se2d[s][i + k];
        sa1 += e1b * se2d[s][i + 1 + k];
        sb0 += e1a * se2d[s][i + k2];
        sb1 += e1b * se2d[s][i + 1 + k2];
    }
    const float acc  = (sa0 + sa1) * eMk;
    const float acc2 = (sb0 + sb1) * eMk2;

    // ---- warp reductions: tot, v0, v1 (fused butterflies) ----
    float tp = acc + (has2 ? acc2 : 0.f);
    float v0 = acc * popc + (has2 ? acc2 * popc2 : 0.f);
    float v1 = acc * pops + (has2 ? acc2 * pops2 : 0.f);
    #pragma unroll
    for (int off = 16; off; off >>= 1) {
        tp += __shfl_xor_sync(0xFFFFFFFFu, tp, off);
        v0 += __shfl_xor_sync(0xFFFFFFFFu, v0, off);
        v1 += __shfl_xor_sync(0xFFFFFFFFu, v1, off);
    }

    // ---- logpost + vec outputs (independent of T) ----
    float* o = out + (b * SS + s) * NOUT;
    const float lt = __logf(tp);
    o[NB + 2 + k] = __logf(acc) - lt;
    if (has2) o[NB + 2 + k2] = __logf(acc2) - lt;
    if (lane == 0) {
        const float inv = 1.0f / tp;
        float a0 = v0 * inv + 1e-8f;
        float a1 = v1 * inv;
        const float n = sqrtf(a0 * a0 + a1 * a1);
        a0 /= n; a1 /= n;
        o[NB]     = fminf(fmaxf(a0, -1.0f), 1.0f);
        o[NB + 1] = fminf(fmaxf(a1, -1.0f), 1.0f);
    }

    __syncthreads();    // T staging complete (latency hidden by the work above)

    // ---- warped matvec: float4 row reads (conflict-free), si broadcast ----
    {
        const float4* Rk  = (const float4*)(sT + k  * NB);
        const float4* Rk2 = (const float4*)(sT + k2 * NB);
        const float4* Sv  = (const float4*)si[s];
        float w0 = 0.f, w1 = 0.f, w2 = 0.f, w3 = 0.f;
        float u0 = 0.f, u1 = 0.f, u2 = 0.f, u3 = 0.f;
        #pragma unroll
        for (int q = 0; q < NB / 4; q++) {
            const float4 sv  = Sv[q];
            const float4 tv  = Rk[q];
            const float4 tv2 = Rk2[q];
            w0 += tv.x  * sv.x;  w1 += tv.y  * sv.y;
            w2 += tv.z  * sv.z;  w3 += tv.w  * sv.w;
            u0 += tv2.x * sv.x;  u1 += tv2.y * sv.y;
            u2 += tv2.z * sv.z;  u3 += tv2.w * sv.w;
        }
        o[k] = (w0 + w1) + (w2 + w3);
        if (has2) o[k2] = (u0 + u1) + (u2 + u3);
    }
}

extern "C" void kernel_launch(void* const* d_in, const int* in_sizes, int n_in,
                              void* d_out, int out_size)
{
    const float* ll1 = (const float*)d_in[0];   // loglikelihood1 [128,7,36]
    const float* ll2 = (const float*)d_in[1];   // loglikelihood2 [128,7,36]
    const float* inp = (const float*)d_in[2];   // inp            [128,7,36]
    const float* yaw = (const float*)d_in[3];   // yaw            [128]
    const float* T   = (const float*)d_in[4];   // transform_matrices [61,36,36]
    const float* M   = (const float*)d_in[5];   // logprior_rotate_matrix [36,36] (circulant)
    // d_in[6] = template_log — equivalent to k=(j-i)%36 selector; unused
    const float* pop = (const float*)d_in[7];   // population_vector [2,36]
    float* out = (float*)d_out;

    const int B = in_sizes[3];                  // 128
    deepwarping_kernel<<<B, SS * 32>>>(ll1, ll2, inp, yaw, T, M, pop, out);
}

// round 12
// speedup vs baseline: 1.1765x; 1.1765x over previous
#include <cuda_runtime.h>
#include <math.h>

#define NB   36
#define NB2  72
#define SS   7
#define NOUT (2*NB + 2)  // 74

// One block per batch b, 224 threads = 7 warps; warp w handles s=w.
// Lane l owns k=l; lanes 0-3 also own k2=32+l.
// Ordering: yaw -> T-tile LDGs issued FIRST (longest dependent chain);
// input staging / constant loads fill their latency shadow. Single late
// __syncthreads; warp-local shuffle reductions; float4 smem throughout.
__global__ __launch_bounds__(224)
void deepwarping_kernel(const float* __restrict__ ll1,   // [B,S,NB]
                        const float* __restrict__ ll2,   // [B,S,NB]
                        const float* __restrict__ inp,   // [B,S,NB]
                        const float* __restrict__ yaw,   // [B]
                        const float* __restrict__ T,     // [61,NB,NB]
                        const float* __restrict__ M,     // [NB,NB] (circulant)
                        const float* __restrict__ pop,   // [2,NB]
                        float* __restrict__ out)         // [B,S,NOUT]
{
    const int b    = blockIdx.x;
    const int tid  = threadIdx.x;
    const int s    = tid >> 5;              // warp id = s (0..6)
    const int lane = tid & 31;

    __shared__ float sT  [NB * NB];         // yaw-selected transform, unpadded
    __shared__ float se1 [SS][NB];          // exp(ll1), per-warp row
    __shared__ float se2d[SS][NB2];         // exp(ll2) doubled, per-warp row
    __shared__ float si  [SS][NB];          // inp, per-warp row

    // ---- longest dependent chain FIRST: yaw -> idx -> T tile loads ----
    const float yv  = __ldg(yaw + b);
    const int   idx = 30 + (int)rintf(yv * (180.0f / 3.14159265358979323846f));
    const float4* T4 = (const float4*)(T + idx * NB * NB);
    // 324 float4 over 224 threads: thread tid takes t0=tid, t1=tid+224 (if <324)
    const bool  tb   = tid < (NB * NB) / 4 - 224;   // tid < 100
    float4 tv0 = T4[tid];
    float4 tv1 = tb ? T4[tid + 224] : make_float4(0.f, 0.f, 0.f, 0.f);

    // ---- independent loads fill the shadow ----
    const int  k    = lane;
    const int  k2   = 32 + (lane & 3);
    const bool has2 = lane < 4;
    const int  base = (b * SS + s) * NB;    // 16B-aligned

    const float eMk   = __expf(__ldg(M + k));     // circulant: M[0][k]
    const float eMk2  = __expf(__ldg(M + k2));
    const float popc  = __ldg(pop + k);
    const float pops  = __ldg(pop + NB + k);
    const float popc2 = __ldg(pop + k2);
    const float pops2 = __ldg(pop + NB + k2);

    // per-warp input staging: lanes 0-8 ll1, 9-17 ll2(doubled), 18-26 inp
    if (lane < 9) {
        float4 a = ((const float4*)(ll1 + base))[lane];
        ((float4*)se1[s])[lane] =
            make_float4(__expf(a.x), __expf(a.y), __expf(a.z), __expf(a.w));
    } else if (lane < 18) {
        const int q = lane - 9;
        float4 c = ((const float4*)(ll2 + base))[q];
        float4 e = make_float4(__expf(c.x), __expf(c.y), __expf(c.z), __expf(c.w));
        ((float4*)(se2d[s]))[q]      = e;
        ((float4*)(se2d[s] + NB))[q] = e;
    } else if (lane < 27) {
        const int q = lane - 18;
        ((float4*)si[s])[q] = ((const float4*)(inp + base))[q];
    }

    // commit T tile to smem (loads issued way above; STS when data lands)
    {
        float4* S4 = (float4*)sT;
        S4[tid] = tv0;
        if (tb) S4[tid + 224] = tv1;
    }

    __syncwarp();   // per-warp input rows ready

    // ---- s_k (and s_k2) : circular cross-correlation, wrap-free ----
    float sa0 = 0.f, sa1 = 0.f, sb0 = 0.f, sb1 = 0.f;
    #pragma unroll
    for (int i = 0; i < NB; i += 2) {
        const float e1a = se1[s][i];
        const float e1b = se1[s][i + 1];
        sa0 += e1a * se2d[s][i + k];
        sa1 += e1b * se2d[s][i + 1 + k];
        sb0 += e1a * se2d[s][i + k2];
        sb1 += e1b * se2d[s][i + 1 + k2];
    }
    const float acc  = (sa0 + sa1) * eMk;
    const float acc2 = (sb0 + sb1) * eMk2;

    // ---- warp reductions: tot, v0, v1 (fused butterflies) ----
    float tp = acc + (has2 ? acc2 : 0.f);
    float v0 = acc * popc + (has2 ? acc2 * popc2 : 0.f);
    float v1 = acc * pops + (has2 ? acc2 * pops2 : 0.f);
    #pragma unroll
    for (int off = 16; off; off >>= 1) {
        tp += __shfl_xor_sync(0xFFFFFFFFu, tp, off);
        v0 += __shfl_xor_sync(0xFFFFFFFFu, v0, off);
        v1 += __shfl_xor_sync(0xFFFFFFFFu, v1, off);
    }

    // ---- logpost + vec outputs (independent of T) ----
    float* o = out + (b * SS + s) * NOUT;
    const float lt = __logf(tp);
    o[NB + 2 + k] = __logf(acc) - lt;
    if (has2) o[NB + 2 + k2] = __logf(acc2) - lt;
    if (lane == 0) {
        const float inv = 1.0f / tp;
        float a0 = v0 * inv + 1e-8f;
        float a1 = v1 * inv;
        const float n = sqrtf(a0 * a0 + a1 * a1);
        a0 /= n; a1 /= n;
        o[NB]     = fminf(fmaxf(a0, -1.0f), 1.0f);
        o[NB + 1] = fminf(fmaxf(a1, -1.0f), 1.0f);
    }

    __syncthreads();    // T tile committed (latency hidden by the work above)

    // ---- warped matvec: float4 row reads (stride-36 rows are LDS.128
    //      conflict-free: banks 4l..4l+3 cover all 32 per 8-lane phase) ----
    {
        const float4* Rk  = (const float4*)(sT + k  * NB);
        const float4* Rk2 = (const float4*)(sT + k2 * NB);
        const float4* Sv  = (const float4*)si[s];
        float w0 = 0.f, w1 = 0.f, w2 = 0.f, w3 = 0.f;
        float u0 = 0.f, u1 = 0.f, u2 = 0.f, u3 = 0.f;
        #pragma unroll
        for (int q = 0; q < NB / 4; q++) {
            const float4 sv  = Sv[q];
            const float4 tv  = Rk[q];
            const float4 tw  = Rk2[q];
            w0 += tv.x * sv.x;  w1 += tv.y * sv.y;
            w2 += tv.z * sv.z;  w3 += tv.w * sv.w;
            u0 += tw.x * sv.x;  u1 += tw.y * sv.y;
            u2 += tw.z * sv.z;  u3 += tw.w * sv.w;
        }
        o[k] = (w0 + w1) + (w2 + w3);
        if (has2) o[k2] = (u0 + u1) + (u2 + u3);
    }
}

extern "C" void kernel_launch(void* const* d_in, const int* in_sizes, int n_in,
                              void* d_out, int out_size)
{
    const float* ll1 = (const float*)d_in[0];   // loglikelihood1 [128,7,36]
    const float* ll2 = (const float*)d_in[1];   // loglikelihood2 [128,7,36]
    const float* inp = (const float*)d_in[2];   // inp            [128,7,36]
    const float* yaw = (const float*)d_in[3];   // yaw            [128]
    const float* T   = (const float*)d_in[4];   // transform_matrices [61,36,36]
    const float* M   = (const float*)d_in[5];   // logprior_rotate_matrix [36,36] (circulant)
    // d_in[6] = template_log — equivalent to k=(j-i)%36 selector; unused
    const float* pop = (const float*)d_in[7];   // population_vector [2,36]
    float* out = (float*)d_out;

    const int B = in_sizes[3];                  // 128
    deepwarping_kernel<<<B, SS * 32>>>(ll1, ll2, inp, yaw, T, M, pop, out);
}